// round 6
// baseline (speedup 1.0000x reference)
#include <cuda_runtime.h>
#include <cuda_bf16.h>

// RoiPoolingLayer: image (1,128,128,512) fp32 NHWC, RoI (1000,4) fp32 [cx,cy,w,h]
// out (1,1000,7,7,512) fp32.
//
// One block per RoI. Threads 0..48 precompute the 49 pooled points' bilinear
// weights and 4 source-pixel base offsets into shared memory once; then all
// 256 threads stream the 49*128 float4 outputs with a lean load/blend/store
// loop (the previous version recomputed the uniform coordinate math in every
// thread of every block, making the kernel issue-bound at 69.7%).

#define H_IMG 128
#define W_IMG 128
#define C4    128          // 512 channels / 4 per float4
#define POOL  7
#define NROI  1000
#define NPTS  49           // POOL*POOL
#define WORK  (NPTS * C4)  // 6272 float4 outputs per RoI
#define STRIDE_F 16.0f

__device__ __forceinline__ void axis_coords(float start, float size, int p, int limit,
                                            int& i0, int& i1, float& frac) {
    // matches reference _axis_coords: half-pixel bilinear resize coords, fp32
    float grid = ((float)p + 0.5f) / (float)POOL;
    float s = grid * size - 0.5f;
    s = fminf(fmaxf(s, 0.0f), size - 1.0f);
    float f0 = floorf(s);
    frac = s - f0;
    float f1 = fminf(f0 + 1.0f, size - 1.0f);
    float lim = (float)(limit - 1);
    i0 = (int)fminf(fmaxf(start + f0, 0.0f), lim);
    i1 = (int)fminf(fmaxf(start + f1, 0.0f), lim);
}

__global__ __launch_bounds__(256) void roi_pool_kernel(
    const float4* __restrict__ f4,    // [128*128*128] float4 view of feat
    const float*  __restrict__ roi,   // [1000,4]
    float4*       __restrict__ o4)    // [1000*49*128] float4 view of out
{
    __shared__ float4 s_w[NPTS];      // w00,w01,w10,w11 per point
    __shared__ int4   s_b[NPTS];      // b00,b01,b10,b11 per point (float4 units)

    const int n   = blockIdx.x;       // 0..999
    const int tid = threadIdx.x;      // 0..255

    if (tid < NPTS) {
        const float x = roi[n * 4 + 0];
        const float y = roi[n * 4 + 1];
        const float w = roi[n * 4 + 2];
        const float h = roi[n * 4 + 3];

        // jnp.round == round-half-to-even == rintf (default RN mode)
        const float r  = rintf((x - w * 0.5f) / STRIDE_F);
        const float c  = rintf((y - h * 0.5f) / STRIDE_F);
        const float wq = fmaxf(rintf(w / STRIDE_F), 1.0f);
        const float hq = fmaxf(rintf(h / STRIDE_F), 1.0f);

        const int py = tid / POOL;
        const int px = tid % POOL;

        int iy0, iy1, ix0, ix1;
        float ly, lx;
        axis_coords(c, hq, py, H_IMG, iy0, iy1, ly);
        axis_coords(r, wq, px, W_IMG, ix0, ix1, lx);

        float4 W;
        W.x = (1.0f - ly) * (1.0f - lx);
        W.y = (1.0f - ly) * lx;
        W.z = ly * (1.0f - lx);
        W.w = ly * lx;
        s_w[tid] = W;

        int4 B;
        B.x = (iy0 * W_IMG + ix0) * C4;
        B.y = (iy0 * W_IMG + ix1) * C4;
        B.z = (iy1 * W_IMG + ix0) * C4;
        B.w = (iy1 * W_IMG + ix1) * C4;
        s_b[tid] = B;
    }
    __syncthreads();

    float4* __restrict__ ob = o4 + (size_t)n * WORK;

    #pragma unroll 2
    for (int idx = tid; idx < WORK; idx += 256) {
        const int p = idx >> 7;        // point 0..48
        const int t = idx & 127;       // float4 channel chunk

        const float4 W = s_w[p];       // broadcast LDS.128 (conflict-free)
        const int4   B = s_b[p];

        const float4 v00 = f4[B.x + t];
        const float4 v01 = f4[B.y + t];
        const float4 v10 = f4[B.z + t];
        const float4 v11 = f4[B.w + t];

        float4 o;
        o.x = W.x * v00.x + W.y * v01.x + W.z * v10.x + W.w * v11.x;
        o.y = W.x * v00.y + W.y * v01.y + W.z * v10.y + W.w * v11.y;
        o.z = W.x * v00.z + W.y * v01.z + W.z * v10.z + W.w * v11.z;
        o.w = W.x * v00.w + W.y * v01.w + W.z * v10.w + W.w * v11.w;

        ob[idx] = o;
    }
}

extern "C" void kernel_launch(void* const* d_in, const int* in_sizes, int n_in,
                              void* d_out, int out_size) {
    const float4* image = (const float4*)d_in[0];  // 1*128*128*512 fp32
    const float*  roi   = (const float*)d_in[1];   // 1000*4 fp32
    float4* out = (float4*)d_out;                  // 1*1000*7*7*512 fp32

    roi_pool_kernel<<<NROI, 256>>>(image, roi, out);
}